// round 11
// baseline (speedup 1.0000x reference)
#include <cuda_runtime.h>
#include <cuda_fp16.h>
#include <math.h>

#define NN 30000
#define EE 300000
#define RR 3
#define KIN 256
#define F1 128   // HEADS*HID
#define F2 256   // HEADS*OUT

// ---------------- scratch (device globals; no allocation allowed) ----------
__device__ __align__(16) __half g_z1h[(size_t)RR * NN * F1];   // 23 MB fp16
__device__ __align__(16) __half g_z2h[(size_t)RR * NN * F2];   // 46 MB fp16
__device__ __align__(16) float  g_h[(size_t)NN * F1];          // 15 MB fp32
__device__ __align__(16) float g_el1[RR * NN * 4];
__device__ __align__(16) float g_er1[RR * NN * 4];
__device__ __align__(16) float g_el2[RR * NN * 4];
__device__ __align__(16) float g_er2[RR * NN * 4];
__device__ int g_deg[RR * NN];
__device__ int g_cur[RR * NN];
__device__ int g_rowoff[RR * (NN + 1)];
__device__ int g_col[RR * EE];

__device__ __forceinline__ float lrelu(float x) { return x > 0.f ? x : 0.2f * x; }

__device__ __forceinline__ unsigned f2tf32(float v) {
    unsigned u;
    asm("cvt.rna.tf32.f32 %0, %1;" : "=r"(u) : "f"(v));
    return u;
}

// ---------------- CSR build --------------------------------------------------
__global__ void k_zero() {
    int i = blockIdx.x * blockDim.x + threadIdx.x;
    if (i < RR * NN) { g_deg[i] = 0; g_cur[i] = 0; }
}

__global__ void k_hist(const int* __restrict__ dst) {
    int i = blockIdx.x * blockDim.x + threadIdx.x;
    if (i < RR * EE) {
        int r = i / EE;
        atomicAdd(&g_deg[r * NN + dst[i]], 1);
    }
}

__global__ void k_scan() {
    int r = blockIdx.x;
    __shared__ int sh[1024];
    __shared__ int carry;
    int t = threadIdx.x;
    if (t == 0) { carry = 0; g_rowoff[r * (NN + 1)] = 0; }
    __syncthreads();
    for (int base = 0; base < NN; base += 1024) {
        int i = base + t;
        int v = (i < NN) ? g_deg[r * NN + i] : 0;
        sh[t] = v;
        __syncthreads();
        for (int off = 1; off < 1024; off <<= 1) {
            int x = (t >= off) ? sh[t - off] : 0;
            __syncthreads();
            sh[t] += x;
            __syncthreads();
        }
        if (i < NN) g_rowoff[r * (NN + 1) + i + 1] = carry + sh[t];
        __syncthreads();
        if (t == 0) carry += sh[1023];
        __syncthreads();
    }
}

__global__ void k_scatter(const int* __restrict__ src, const int* __restrict__ dst) {
    int i = blockIdx.x * blockDim.x + threadIdx.x;
    if (i < RR * EE) {
        int r = i / EE;
        int d = dst[i];
        int pos = atomicAdd(&g_cur[r * NN + d], 1);
        g_col[(size_t)r * EE + g_rowoff[r * (NN + 1) + d] + pos] = src[i];
    }
}

// ---------------- TF32 tensor-core GEMM: C[r] = A @ B[r], fp16 output --------
#define SSTR 132

__global__ __launch_bounds__(256, 2)
void k_sgemm_tf32(const float* __restrict__ Aext, const float* __restrict__ Bg,
                  int M, int K, int Nc, int layer) {
    const float* A = (layer == 1) ? Aext : g_h;
    int r = blockIdx.z;
    const float* B = Bg + (size_t)r * K * Nc;

    __shared__ unsigned As[2][16 * SSTR];   // [k][m]
    __shared__ unsigned Bs[2][16 * SSTR];   // [k][n]

    int tid = threadIdx.x;
    int lane = tid & 31;
    int wid = tid >> 5;
    int wm = (wid & 1) * 64;
    int wn = (wid >> 1) * 32;
    int gid = lane >> 2;
    int tig = lane & 3;

    int row0 = blockIdx.y * 128, col0 = blockIdx.x * 128;

    int am = tid >> 2;
    int ak = (tid & 3) * 4;
    int bk = tid >> 4;
    int bn = (tid & 15) * 4;

    float acc[4][4][4];
#pragma unroll
    for (int i = 0; i < 4; i++)
#pragma unroll
        for (int j = 0; j < 4; j++)
#pragma unroll
            for (int q = 0; q < 4; q++) acc[i][j][q] = 0.f;

    int nstage = K >> 4;

    {
        float4 va0, va1, vb0, vb1;
        int gr0 = row0 + am, gr1 = row0 + am + 64;
        va0 = (gr0 < M) ? *reinterpret_cast<const float4*>(&A[(size_t)gr0 * K + ak])
                        : make_float4(0, 0, 0, 0);
        va1 = (gr1 < M) ? *reinterpret_cast<const float4*>(&A[(size_t)gr1 * K + ak])
                        : make_float4(0, 0, 0, 0);
        vb0 = *reinterpret_cast<const float4*>(&B[(size_t)bk * Nc + col0 + bn]);
        vb1 = *reinterpret_cast<const float4*>(&B[(size_t)bk * Nc + col0 + 64 + bn]);
        As[0][(ak + 0) * SSTR + am] = f2tf32(va0.x);
        As[0][(ak + 1) * SSTR + am] = f2tf32(va0.y);
        As[0][(ak + 2) * SSTR + am] = f2tf32(va0.z);
        As[0][(ak + 3) * SSTR + am] = f2tf32(va0.w);
        As[0][(ak + 0) * SSTR + am + 64] = f2tf32(va1.x);
        As[0][(ak + 1) * SSTR + am + 64] = f2tf32(va1.y);
        As[0][(ak + 2) * SSTR + am + 64] = f2tf32(va1.z);
        As[0][(ak + 3) * SSTR + am + 64] = f2tf32(va1.w);
        Bs[0][bk * SSTR + bn + 0] = f2tf32(vb0.x);
        Bs[0][bk * SSTR + bn + 1] = f2tf32(vb0.y);
        Bs[0][bk * SSTR + bn + 2] = f2tf32(vb0.z);
        Bs[0][bk * SSTR + bn + 3] = f2tf32(vb0.w);
        Bs[0][bk * SSTR + 64 + bn + 0] = f2tf32(vb1.x);
        Bs[0][bk * SSTR + 64 + bn + 1] = f2tf32(vb1.y);
        Bs[0][bk * SSTR + 64 + bn + 2] = f2tf32(vb1.z);
        Bs[0][bk * SSTR + 64 + bn + 3] = f2tf32(vb1.w);
    }
    __syncthreads();

    int buf = 0;
    for (int s = 0; s < nstage; s++) {
        float4 va0, va1, vb0, vb1;
        bool more = (s + 1) < nstage;
        if (more) {
            int k0 = (s + 1) << 4;
            int gr0 = row0 + am, gr1 = row0 + am + 64;
            va0 = (gr0 < M) ? *reinterpret_cast<const float4*>(&A[(size_t)gr0 * K + k0 + ak])
                            : make_float4(0, 0, 0, 0);
            va1 = (gr1 < M) ? *reinterpret_cast<const float4*>(&A[(size_t)gr1 * K + k0 + ak])
                            : make_float4(0, 0, 0, 0);
            vb0 = *reinterpret_cast<const float4*>(&B[(size_t)(k0 + bk) * Nc + col0 + bn]);
            vb1 = *reinterpret_cast<const float4*>(&B[(size_t)(k0 + bk) * Nc + col0 + 64 + bn]);
        }

        const unsigned* as = As[buf];
        const unsigned* bs = Bs[buf];
#pragma unroll
        for (int kk = 0; kk < 16; kk += 8) {
            unsigned a[4][4], b[4][2];
#pragma unroll
            for (int i = 0; i < 4; i++) {
                int m = wm + i * 16 + gid;
                a[i][0] = as[(kk + tig) * SSTR + m];
                a[i][1] = as[(kk + tig) * SSTR + m + 8];
                a[i][2] = as[(kk + tig + 4) * SSTR + m];
                a[i][3] = as[(kk + tig + 4) * SSTR + m + 8];
            }
#pragma unroll
            for (int j = 0; j < 4; j++) {
                int n = wn + j * 8 + gid;
                b[j][0] = bs[(kk + tig) * SSTR + n];
                b[j][1] = bs[(kk + tig + 4) * SSTR + n];
            }
#pragma unroll
            for (int i = 0; i < 4; i++)
#pragma unroll
                for (int j = 0; j < 4; j++) {
                    asm volatile(
                        "mma.sync.aligned.m16n8k8.row.col.f32.tf32.tf32.f32 "
                        "{%0,%1,%2,%3}, {%4,%5,%6,%7}, {%8,%9}, {%0,%1,%2,%3};\n"
                        : "+f"(acc[i][j][0]), "+f"(acc[i][j][1]),
                          "+f"(acc[i][j][2]), "+f"(acc[i][j][3])
                        : "r"(a[i][0]), "r"(a[i][1]), "r"(a[i][2]), "r"(a[i][3]),
                          "r"(b[j][0]), "r"(b[j][1]));
                }
        }

        if (more) {
            unsigned* asn = As[buf ^ 1];
            unsigned* bsn = Bs[buf ^ 1];
            asn[(ak + 0) * SSTR + am] = f2tf32(va0.x);
            asn[(ak + 1) * SSTR + am] = f2tf32(va0.y);
            asn[(ak + 2) * SSTR + am] = f2tf32(va0.z);
            asn[(ak + 3) * SSTR + am] = f2tf32(va0.w);
            asn[(ak + 0) * SSTR + am + 64] = f2tf32(va1.x);
            asn[(ak + 1) * SSTR + am + 64] = f2tf32(va1.y);
            asn[(ak + 2) * SSTR + am + 64] = f2tf32(va1.z);
            asn[(ak + 3) * SSTR + am + 64] = f2tf32(va1.w);
            bsn[bk * SSTR + bn + 0] = f2tf32(vb0.x);
            bsn[bk * SSTR + bn + 1] = f2tf32(vb0.y);
            bsn[bk * SSTR + bn + 2] = f2tf32(vb0.z);
            bsn[bk * SSTR + bn + 3] = f2tf32(vb0.w);
            bsn[bk * SSTR + 64 + bn + 0] = f2tf32(vb1.x);
            bsn[bk * SSTR + 64 + bn + 1] = f2tf32(vb1.y);
            bsn[bk * SSTR + 64 + bn + 2] = f2tf32(vb1.z);
            bsn[bk * SSTR + 64 + bn + 3] = f2tf32(vb1.w);
        }
        __syncthreads();
        buf ^= 1;
    }

    __half* C = ((layer == 1) ? g_z1h : g_z2h) + (size_t)r * M * Nc;
#pragma unroll
    for (int i = 0; i < 4; i++)
#pragma unroll
        for (int j = 0; j < 4; j++) {
            int gr = row0 + wm + i * 16 + gid;
            int gc = col0 + wn + j * 8 + 2 * tig;
            if (gr < M)
                *reinterpret_cast<__half2*>(&C[(size_t)gr * Nc + gc]) =
                    __floats2half2_rn(acc[i][j][0], acc[i][j][1]);
            if (gr + 8 < M)
                *reinterpret_cast<__half2*>(&C[(size_t)(gr + 8) * Nc + gc]) =
                    __floats2half2_rn(acc[i][j][2], acc[i][j][3]);
        }
}

// ---------------- attention projections: warp per (node, relation) -----------
// attn1 (fp16 z1): lane handles cols 4*lane..4*lane+3; head = lane>>3
__global__ void k_attn1(const float* __restrict__ al, const float* __restrict__ ar) {
    int gw = (blockIdx.x * blockDim.x + threadIdx.x) >> 5;
    if (gw >= NN * RR) return;
    int r = gw / NN, n = gw - r * NN;
    int lane = threadIdx.x & 31;
    const __half2* zp = reinterpret_cast<const __half2*>(
        &g_z1h[((size_t)(r * NN + n)) * F1 + lane * 4]);
    float2 f0 = __half22float2(zp[0]);
    float2 f1 = __half22float2(zp[1]);
    float4 a4 = *reinterpret_cast<const float4*>(&al[r * F1 + lane * 4]);
    float4 r4 = *reinterpret_cast<const float4*>(&ar[r * F1 + lane * 4]);
    float pl = f0.x * a4.x + f0.y * a4.y + f1.x * a4.z + f1.y * a4.w;
    float pr = f0.x * r4.x + f0.y * r4.y + f1.x * r4.z + f1.y * r4.w;
#pragma unroll
    for (int o = 4; o > 0; o >>= 1) {
        pl += __shfl_xor_sync(0xffffffffu, pl, o);
        pr += __shfl_xor_sync(0xffffffffu, pr, o);
    }
    if ((lane & 7) == 0) {
        int h = lane >> 3;
        g_el1[(r * NN + n) * 4 + h] = pl;
        g_er1[(r * NN + n) * 4 + h] = pr;
    }
}

// attn2 (fp16 z2): lane handles 8 cols
__global__ void k_attn2(const float* __restrict__ al, const float* __restrict__ ar) {
    int gw = (blockIdx.x * blockDim.x + threadIdx.x) >> 5;
    if (gw >= NN * RR) return;
    int r = gw / NN, n = gw - r * NN;
    int lane = threadIdx.x & 31;
    const __half2* zp = reinterpret_cast<const __half2*>(
        &g_z2h[((size_t)(r * NN + n)) * F2 + lane * 8]);
    float z[8];
#pragma unroll
    for (int q = 0; q < 4; q++) {
        float2 f = __half22float2(zp[q]);
        z[2 * q] = f.x; z[2 * q + 1] = f.y;
    }
    const float* ap = &al[r * F2 + lane * 8];
    const float* rp = &ar[r * F2 + lane * 8];
    float4 a0 = *reinterpret_cast<const float4*>(ap);
    float4 a1 = *reinterpret_cast<const float4*>(ap + 4);
    float4 r0 = *reinterpret_cast<const float4*>(rp);
    float4 r1 = *reinterpret_cast<const float4*>(rp + 4);
    float pl = z[0] * a0.x + z[1] * a0.y + z[2] * a0.z + z[3] * a0.w
             + z[4] * a1.x + z[5] * a1.y + z[6] * a1.z + z[7] * a1.w;
    float pr = z[0] * r0.x + z[1] * r0.y + z[2] * r0.z + z[3] * r0.w
             + z[4] * r1.x + z[5] * r1.y + z[6] * r1.z + z[7] * r1.w;
#pragma unroll
    for (int o = 4; o > 0; o >>= 1) {
        pl += __shfl_xor_sync(0xffffffffu, pl, o);
        pr += __shfl_xor_sync(0xffffffffu, pr, o);
    }
    if ((lane & 7) == 0) {
        int h = lane >> 3;
        g_el2[(r * NN + n) * 4 + h] = pl;
        g_er2[(r * NN + n) * 4 + h] = pr;
    }
}

// ------- layer-1 agg (fp16 z1): lane owns cols {2l,2l+1} (heads 0/1) and
//         {64+2l, 64+2l+1} (heads 2/3); head picked by lane<16 ---------------
__global__ void k_agg1(const float* __restrict__ b1) {
    int w = (blockIdx.x * blockDim.x + threadIdx.x) >> 5;
    int lane = threadIdx.x & 31;
    if (w >= NN) return;
    int n = w;
    bool lo16 = (lane < 16);
    float tl0 = 0.f, tl1 = 0.f, th0 = 0.f, th1 = 0.f;
#pragma unroll
    for (int r = 0; r < RR; r++) {
        int beg = g_rowoff[r * (NN + 1) + n];
        int end = g_rowoff[r * (NN + 1) + n + 1];
        if (beg == end) continue;
        const float4 erd = *reinterpret_cast<const float4*>(&g_er1[(r * NN + n) * 4]);
        float d0 = 0, d1 = 0, d2 = 0, d3 = 0;
        float al0 = 0, al1 = 0, ah0 = 0, ah1 = 0;
        for (int i = beg; i < end; i++) {
            int s = g_col[(size_t)r * EE + i];
            float4 el = *reinterpret_cast<const float4*>(&g_el1[(r * NN + s) * 4]);
            float w0 = __expf(lrelu(el.x + erd.x));
            float w1 = __expf(lrelu(el.y + erd.y));
            float w2 = __expf(lrelu(el.z + erd.z));
            float w3 = __expf(lrelu(el.w + erd.w));
            d0 += w0; d1 += w1; d2 += w2; d3 += w3;
            const __half2* z = reinterpret_cast<const __half2*>(
                &g_z1h[((size_t)(r * NN + s)) * F1]);
            float2 flo = __half22float2(z[lane]);        // cols 2l..2l+1 (head lane>>4)
            float2 fhi = __half22float2(z[32 + lane]);   // cols 64+2l..   (head 2+lane>>4)
            float wl = lo16 ? w0 : w1;
            float wh = lo16 ? w2 : w3;
            al0 += wl * flo.x; al1 += wl * flo.y;
            ah0 += wh * fhi.x; ah1 += wh * fhi.y;
        }
        float dl = lo16 ? d0 : d1;
        float dh = lo16 ? d2 : d3;
        tl0 += al0 / dl; tl1 += al1 / dl;
        th0 += ah0 / dh; th1 += ah1 / dh;
    }
    int c0 = 2 * lane, c1 = 2 * lane + 1;
    tl0 += b1[c0]      + b1[F1 + c0]      + b1[2 * F1 + c0];
    tl1 += b1[c1]      + b1[F1 + c1]      + b1[2 * F1 + c1];
    th0 += b1[64 + c0] + b1[F1 + 64 + c0] + b1[2 * F1 + 64 + c0];
    th1 += b1[64 + c1] + b1[F1 + 64 + c1] + b1[2 * F1 + 64 + c1];
    size_t o = (size_t)n * F1;
    *reinterpret_cast<float2*>(&g_h[o + c0]) =
        make_float2(fmaxf(tl0, 0.f), fmaxf(tl1, 0.f));
    *reinterpret_cast<float2*>(&g_h[o + 64 + c0]) =
        make_float2(fmaxf(th0, 0.f), fmaxf(th1, 0.f));
}

// ------- layer-2 agg (fp16 z2): lane owns out cols {2*lane, 2*lane+1} --------
__global__ void k_agg2(const float* __restrict__ b2, float* __restrict__ out) {
    int w = (blockIdx.x * blockDim.x + threadIdx.x) >> 5;
    int lane = threadIdx.x & 31;
    if (w >= NN) return;
    int n = w;
    float t00 = 0, t01 = 0, t10 = 0, t11 = 0, t20 = 0, t21 = 0, t30 = 0, t31 = 0;
#pragma unroll
    for (int r = 0; r < RR; r++) {
        int beg = g_rowoff[r * (NN + 1) + n];
        int end = g_rowoff[r * (NN + 1) + n + 1];
        if (beg == end) continue;
        const float4 erd = *reinterpret_cast<const float4*>(&g_er2[(r * NN + n) * 4]);
        float d0 = 0, d1 = 0, d2 = 0, d3 = 0;
        float a00 = 0, a01 = 0, a10 = 0, a11 = 0, a20 = 0, a21 = 0, a30 = 0, a31 = 0;
        for (int i = beg; i < end; i++) {
            int s = g_col[(size_t)r * EE + i];
            float4 el = *reinterpret_cast<const float4*>(&g_el2[(r * NN + s) * 4]);
            float w0 = __expf(lrelu(el.x + erd.x));
            float w1 = __expf(lrelu(el.y + erd.y));
            float w2 = __expf(lrelu(el.z + erd.z));
            float w3 = __expf(lrelu(el.w + erd.w));
            d0 += w0; d1 += w1; d2 += w2; d3 += w3;
            const __half2* z = reinterpret_cast<const __half2*>(
                &g_z2h[((size_t)(r * NN + s)) * F2]);
            float2 f0 = __half22float2(z[lane]);
            float2 f1 = __half22float2(z[32 + lane]);
            float2 f2 = __half22float2(z[64 + lane]);
            float2 f3 = __half22float2(z[96 + lane]);
            a00 += w0 * f0.x; a01 += w0 * f0.y;
            a10 += w1 * f1.x; a11 += w1 * f1.y;
            a20 += w2 * f2.x; a21 += w2 * f2.y;
            a30 += w3 * f3.x; a31 += w3 * f3.y;
        }
        t00 += a00 / d0; t01 += a01 / d0;
        t10 += a10 / d1; t11 += a11 / d1;
        t20 += a20 / d2; t21 += a21 / d2;
        t30 += a30 / d3; t31 += a31 / d3;
    }
    int c0 = 2 * lane, c1 = 2 * lane + 1;
    t00 += b2[c0]       + b2[F2 + c0]       + b2[2 * F2 + c0];
    t01 += b2[c1]       + b2[F2 + c1]       + b2[2 * F2 + c1];
    t10 += b2[64 + c0]  + b2[F2 + 64 + c0]  + b2[2 * F2 + 64 + c0];
    t11 += b2[64 + c1]  + b2[F2 + 64 + c1]  + b2[2 * F2 + 64 + c1];
    t20 += b2[128 + c0] + b2[F2 + 128 + c0] + b2[2 * F2 + 128 + c0];
    t21 += b2[128 + c1] + b2[F2 + 128 + c1] + b2[2 * F2 + 128 + c1];
    t30 += b2[192 + c0] + b2[F2 + 192 + c0] + b2[2 * F2 + 192 + c0];
    t31 += b2[192 + c1] + b2[F2 + 192 + c1] + b2[2 * F2 + 192 + c1];
    *reinterpret_cast<float2*>(&out[(size_t)n * 64 + c0]) =
        make_float2(0.25f * (t00 + t10 + t20 + t30),
                    0.25f * (t01 + t11 + t21 + t31));
}

// ---------------- launch (single stream) -------------------------------------
extern "C" void kernel_launch(void* const* d_in, const int* in_sizes, int n_in,
                              void* d_out, int out_size) {
    const float* x   = (const float*)d_in[0];
    const int*   src = (const int*)d_in[1];
    const int*   dst = (const int*)d_in[2];
    const float* W1  = (const float*)d_in[3];
    const float* al1 = (const float*)d_in[4];
    const float* ar1 = (const float*)d_in[5];
    const float* b1  = (const float*)d_in[6];
    const float* W2  = (const float*)d_in[7];
    const float* al2 = (const float*)d_in[8];
    const float* ar2 = (const float*)d_in[9];
    const float* b2  = (const float*)d_in[10];
    float* out = (float*)d_out;

    // CSR by dst, per relation
    k_zero<<<(RR * NN + 255) / 256, 256>>>();
    k_hist<<<(RR * EE + 255) / 256, 256>>>(dst);
    k_scan<<<RR, 1024>>>();
    k_scatter<<<(RR * EE + 255) / 256, 256>>>(src, dst);

    // layer 1
    dim3 g1(F1 / 128, (NN + 127) / 128, RR);
    k_sgemm_tf32<<<g1, 256>>>(x, W1, NN, KIN, F1, 1);
    k_attn1<<<(NN * RR + 7) / 8, 256>>>(al1, ar1);
    k_agg1<<<(NN + 3) / 4, 128>>>(b1);

    // layer 2
    dim3 g2(F2 / 128, (NN + 127) / 128, RR);
    k_sgemm_tf32<<<g2, 256>>>(nullptr, W2, NN, F1, F2, 2);
    k_attn2<<<(NN * RR + 7) / 8, 256>>>(al2, ar2);
    k_agg2<<<(NN + 3) / 4, 128>>>(b2, out);
}

// round 12
// speedup vs baseline: 1.0644x; 1.0644x over previous
#include <cuda_runtime.h>
#include <cuda_fp16.h>
#include <math.h>

#define NN 30000
#define EE 300000
#define RR 3
#define KIN 256
#define F1 128   // HEADS*HID
#define F2 256   // HEADS*OUT

// ---------------- scratch (device globals; no allocation allowed) ----------
__device__ __align__(16) __half g_z1h[(size_t)RR * NN * F1];   // 23 MB fp16
__device__ __align__(16) __half g_z2h[(size_t)RR * NN * F2];   // 46 MB fp16
__device__ __align__(16) float  g_h[(size_t)NN * F1];          // 15 MB fp32
__device__ __align__(16) __half g_w1t[RR * F1 * KIN];          // W1^T fp16 [r][n][k]
__device__ __align__(16) __half g_w2t[RR * F2 * F1];           // W2^T fp16 [r][n][k]
__device__ __align__(16) float g_el1[RR * NN * 4];
__device__ __align__(16) float g_er1[RR * NN * 4];
__device__ __align__(16) float g_el2[RR * NN * 4];
__device__ __align__(16) float g_er2[RR * NN * 4];
__device__ int g_deg[RR * NN];
__device__ int g_cur[RR * NN];
__device__ int g_rowoff[RR * (NN + 1)];
__device__ int g_col[RR * EE];

__device__ __forceinline__ float lrelu(float x) { return x > 0.f ? x : 0.2f * x; }

// ---------------- CSR build --------------------------------------------------
__global__ void k_zero() {
    int i = blockIdx.x * blockDim.x + threadIdx.x;
    if (i < RR * NN) { g_deg[i] = 0; g_cur[i] = 0; }
}

__global__ void k_hist(const int* __restrict__ dst) {
    int i = blockIdx.x * blockDim.x + threadIdx.x;
    if (i < RR * EE) {
        int r = i / EE;
        atomicAdd(&g_deg[r * NN + dst[i]], 1);
    }
}

__global__ void k_scan() {
    int r = blockIdx.x;
    __shared__ int sh[1024];
    __shared__ int carry;
    int t = threadIdx.x;
    if (t == 0) { carry = 0; g_rowoff[r * (NN + 1)] = 0; }
    __syncthreads();
    for (int base = 0; base < NN; base += 1024) {
        int i = base + t;
        int v = (i < NN) ? g_deg[r * NN + i] : 0;
        sh[t] = v;
        __syncthreads();
        for (int off = 1; off < 1024; off <<= 1) {
            int x = (t >= off) ? sh[t - off] : 0;
            __syncthreads();
            sh[t] += x;
            __syncthreads();
        }
        if (i < NN) g_rowoff[r * (NN + 1) + i + 1] = carry + sh[t];
        __syncthreads();
        if (t == 0) carry += sh[1023];
        __syncthreads();
    }
}

__global__ void k_scatter(const int* __restrict__ src, const int* __restrict__ dst) {
    int i = blockIdx.x * blockDim.x + threadIdx.x;
    if (i < RR * EE) {
        int r = i / EE;
        int d = dst[i];
        int pos = atomicAdd(&g_cur[r * NN + d], 1);
        g_col[(size_t)r * EE + g_rowoff[r * (NN + 1) + d] + pos] = src[i];
    }
}

// ---------------- weight transpose: W[r][k][n] fp32 -> Wt[r][n][k] fp16 ------
__global__ void k_transw(const float* __restrict__ W, __half* __restrict__ Wt,
                         int K, int Nc) {
    int r = blockIdx.y;
    int idx = blockIdx.x * blockDim.x + threadIdx.x;
    if (idx < K * Nc) {
        int k = idx / Nc, n = idx - k * Nc;
        Wt[((size_t)r * Nc + n) * K + k] = __float2half_rn(W[(size_t)r * K * Nc + idx]);
    }
}

// ---------------- fp16 HMMA GEMM: C[r] = A @ Bt[r]^T -------------------------
// Block 128x128, 8 warps (2x4), warp tile 64x32, mma.m16n8k16.f16, BK=16.
// smem [row][k] halves, stride 24 halves (48B) -> conflict-free half2 frags.
#define SH 24

__global__ __launch_bounds__(256, 2)
void k_sgemm_h(const float* __restrict__ Aext, const __half* __restrict__ Btg,
               int M, int K, int Nc, int layer) {
    const float* A = (layer == 1) ? Aext : g_h;
    int r = blockIdx.z;
    const __half* Bt = Btg + (size_t)r * Nc * K;   // [n][k]

    __shared__ __half As[2][128 * SH];
    __shared__ __half Bs[2][128 * SH];

    int tid = threadIdx.x;
    int lane = tid & 31;
    int wid = tid >> 5;
    int wm = (wid & 1) * 64;
    int wn = (wid >> 1) * 32;
    int gid = lane >> 2;
    int tig = lane & 3;

    int row0 = blockIdx.y * 128, col0 = blockIdx.x * 128;

    int arow = tid >> 1;               // 0..127
    int acol = (tid & 1) * 8;          // 0 or 8 (k offset)
    int brow = tid >> 1;
    int bcol = (tid & 1) * 8;

    float acc[4][4][4];
#pragma unroll
    for (int i = 0; i < 4; i++)
#pragma unroll
        for (int j = 0; j < 4; j++)
#pragma unroll
            for (int q = 0; q < 4; q++) acc[i][j][q] = 0.f;

    int nstage = K >> 4;

    // stage loader
    auto load_stage = [&](int sbuf, int k0) {
        int gr = row0 + arow;
        float4 v0, v1;
        if (gr < M) {
            v0 = *reinterpret_cast<const float4*>(&A[(size_t)gr * K + k0 + acol]);
            v1 = *reinterpret_cast<const float4*>(&A[(size_t)gr * K + k0 + acol + 4]);
        } else {
            v0 = make_float4(0, 0, 0, 0);
            v1 = make_float4(0, 0, 0, 0);
        }
        __half2* ap = reinterpret_cast<__half2*>(&As[sbuf][arow * SH + acol]);
        ap[0] = __floats2half2_rn(v0.x, v0.y);
        ap[1] = __floats2half2_rn(v0.z, v0.w);
        ap[2] = __floats2half2_rn(v1.x, v1.y);
        ap[3] = __floats2half2_rn(v1.z, v1.w);
        // B: fp16 gmem row copy
        const uint4 bv = *reinterpret_cast<const uint4*>(
            &Bt[((size_t)(col0 + brow)) * K + k0 + bcol]);
        *reinterpret_cast<uint4*>(&Bs[sbuf][brow * SH + bcol]) = bv;
    };

    load_stage(0, 0);
    __syncthreads();

    int buf = 0;
    for (int s = 0; s < nstage; s++) {
        bool more = (s + 1) < nstage;

        const __half* as = As[buf];
        const __half* bs = Bs[buf];
        unsigned a[4][4], b[4][2];
#pragma unroll
        for (int i = 0; i < 4; i++) {
            int m = wm + i * 16 + gid;
            a[i][0] = *reinterpret_cast<const unsigned*>(&as[m * SH + 2 * tig]);
            a[i][1] = *reinterpret_cast<const unsigned*>(&as[(m + 8) * SH + 2 * tig]);
            a[i][2] = *reinterpret_cast<const unsigned*>(&as[m * SH + 2 * tig + 8]);
            a[i][3] = *reinterpret_cast<const unsigned*>(&as[(m + 8) * SH + 2 * tig + 8]);
        }
#pragma unroll
        for (int j = 0; j < 4; j++) {
            int n = wn + j * 8 + gid;
            b[j][0] = *reinterpret_cast<const unsigned*>(&bs[n * SH + 2 * tig]);
            b[j][1] = *reinterpret_cast<const unsigned*>(&bs[n * SH + 2 * tig + 8]);
        }
#pragma unroll
        for (int i = 0; i < 4; i++)
#pragma unroll
            for (int j = 0; j < 4; j++) {
                asm volatile(
                    "mma.sync.aligned.m16n8k16.row.col.f32.f16.f16.f32 "
                    "{%0,%1,%2,%3}, {%4,%5,%6,%7}, {%8,%9}, {%0,%1,%2,%3};\n"
                    : "+f"(acc[i][j][0]), "+f"(acc[i][j][1]),
                      "+f"(acc[i][j][2]), "+f"(acc[i][j][3])
                    : "r"(a[i][0]), "r"(a[i][1]), "r"(a[i][2]), "r"(a[i][3]),
                      "r"(b[j][0]), "r"(b[j][1]));
            }

        if (more) load_stage(buf ^ 1, (s + 1) << 4);
        __syncthreads();
        buf ^= 1;
    }

    __half* C = ((layer == 1) ? g_z1h : g_z2h) + (size_t)r * M * Nc;
#pragma unroll
    for (int i = 0; i < 4; i++)
#pragma unroll
        for (int j = 0; j < 4; j++) {
            int gr = row0 + wm + i * 16 + gid;
            int gc = col0 + wn + j * 8 + 2 * tig;
            if (gr < M)
                *reinterpret_cast<__half2*>(&C[(size_t)gr * Nc + gc]) =
                    __floats2half2_rn(acc[i][j][0], acc[i][j][1]);
            if (gr + 8 < M)
                *reinterpret_cast<__half2*>(&C[(size_t)(gr + 8) * Nc + gc]) =
                    __floats2half2_rn(acc[i][j][2], acc[i][j][3]);
        }
}

// ---------------- attention projections: warp per (node, relation) -----------
__global__ void k_attn1(const float* __restrict__ al, const float* __restrict__ ar) {
    int gw = (blockIdx.x * blockDim.x + threadIdx.x) >> 5;
    if (gw >= NN * RR) return;
    int r = gw / NN, n = gw - r * NN;
    int lane = threadIdx.x & 31;
    const __half2* zp = reinterpret_cast<const __half2*>(
        &g_z1h[((size_t)(r * NN + n)) * F1 + lane * 4]);
    float2 f0 = __half22float2(zp[0]);
    float2 f1 = __half22float2(zp[1]);
    float4 a4 = *reinterpret_cast<const float4*>(&al[r * F1 + lane * 4]);
    float4 r4 = *reinterpret_cast<const float4*>(&ar[r * F1 + lane * 4]);
    float pl = f0.x * a4.x + f0.y * a4.y + f1.x * a4.z + f1.y * a4.w;
    float pr = f0.x * r4.x + f0.y * r4.y + f1.x * r4.z + f1.y * r4.w;
#pragma unroll
    for (int o = 4; o > 0; o >>= 1) {
        pl += __shfl_xor_sync(0xffffffffu, pl, o);
        pr += __shfl_xor_sync(0xffffffffu, pr, o);
    }
    if ((lane & 7) == 0) {
        int h = lane >> 3;
        g_el1[(r * NN + n) * 4 + h] = pl;
        g_er1[(r * NN + n) * 4 + h] = pr;
    }
}

__global__ void k_attn2(const float* __restrict__ al, const float* __restrict__ ar) {
    int gw = (blockIdx.x * blockDim.x + threadIdx.x) >> 5;
    if (gw >= NN * RR) return;
    int r = gw / NN, n = gw - r * NN;
    int lane = threadIdx.x & 31;
    const __half2* zp = reinterpret_cast<const __half2*>(
        &g_z2h[((size_t)(r * NN + n)) * F2 + lane * 8]);
    float z[8];
#pragma unroll
    for (int q = 0; q < 4; q++) {
        float2 f = __half22float2(zp[q]);
        z[2 * q] = f.x; z[2 * q + 1] = f.y;
    }
    const float* ap = &al[r * F2 + lane * 8];
    const float* rp = &ar[r * F2 + lane * 8];
    float4 a0 = *reinterpret_cast<const float4*>(ap);
    float4 a1 = *reinterpret_cast<const float4*>(ap + 4);
    float4 r0 = *reinterpret_cast<const float4*>(rp);
    float4 r1 = *reinterpret_cast<const float4*>(rp + 4);
    float pl = z[0] * a0.x + z[1] * a0.y + z[2] * a0.z + z[3] * a0.w
             + z[4] * a1.x + z[5] * a1.y + z[6] * a1.z + z[7] * a1.w;
    float pr = z[0] * r0.x + z[1] * r0.y + z[2] * r0.z + z[3] * r0.w
             + z[4] * r1.x + z[5] * r1.y + z[6] * r1.z + z[7] * r1.w;
#pragma unroll
    for (int o = 4; o > 0; o >>= 1) {
        pl += __shfl_xor_sync(0xffffffffu, pl, o);
        pr += __shfl_xor_sync(0xffffffffu, pr, o);
    }
    if ((lane & 7) == 0) {
        int h = lane >> 3;
        g_el2[(r * NN + n) * 4 + h] = pl;
        g_er2[(r * NN + n) * 4 + h] = pr;
    }
}

// ------- layer-1 agg (fp16 z1): lane owns cols {2l,2l+1} and {64+2l,64+2l+1} -
__global__ void k_agg1(const float* __restrict__ b1) {
    int w = (blockIdx.x * blockDim.x + threadIdx.x) >> 5;
    int lane = threadIdx.x & 31;
    if (w >= NN) return;
    int n = w;
    bool lo16 = (lane < 16);
    float tl0 = 0.f, tl1 = 0.f, th0 = 0.f, th1 = 0.f;
#pragma unroll
    for (int r = 0; r < RR; r++) {
        int beg = g_rowoff[r * (NN + 1) + n];
        int end = g_rowoff[r * (NN + 1) + n + 1];
        if (beg == end) continue;
        const float4 erd = *reinterpret_cast<const float4*>(&g_er1[(r * NN + n) * 4]);
        float d0 = 0, d1 = 0, d2 = 0, d3 = 0;
        float al0 = 0, al1 = 0, ah0 = 0, ah1 = 0;
        for (int i = beg; i < end; i++) {
            int s = g_col[(size_t)r * EE + i];
            float4 el = *reinterpret_cast<const float4*>(&g_el1[(r * NN + s) * 4]);
            float w0 = __expf(lrelu(el.x + erd.x));
            float w1 = __expf(lrelu(el.y + erd.y));
            float w2 = __expf(lrelu(el.z + erd.z));
            float w3 = __expf(lrelu(el.w + erd.w));
            d0 += w0; d1 += w1; d2 += w2; d3 += w3;
            const __half2* z = reinterpret_cast<const __half2*>(
                &g_z1h[((size_t)(r * NN + s)) * F1]);
            float2 flo = __half22float2(z[lane]);
            float2 fhi = __half22float2(z[32 + lane]);
            float wl = lo16 ? w0 : w1;
            float wh = lo16 ? w2 : w3;
            al0 += wl * flo.x; al1 += wl * flo.y;
            ah0 += wh * fhi.x; ah1 += wh * fhi.y;
        }
        float dl = lo16 ? d0 : d1;
        float dh = lo16 ? d2 : d3;
        tl0 += al0 / dl; tl1 += al1 / dl;
        th0 += ah0 / dh; th1 += ah1 / dh;
    }
    int c0 = 2 * lane, c1 = 2 * lane + 1;
    tl0 += b1[c0]      + b1[F1 + c0]      + b1[2 * F1 + c0];
    tl1 += b1[c1]      + b1[F1 + c1]      + b1[2 * F1 + c1];
    th0 += b1[64 + c0] + b1[F1 + 64 + c0] + b1[2 * F1 + 64 + c0];
    th1 += b1[64 + c1] + b1[F1 + 64 + c1] + b1[2 * F1 + 64 + c1];
    size_t o = (size_t)n * F1;
    *reinterpret_cast<float2*>(&g_h[o + c0]) =
        make_float2(fmaxf(tl0, 0.f), fmaxf(tl1, 0.f));
    *reinterpret_cast<float2*>(&g_h[o + 64 + c0]) =
        make_float2(fmaxf(th0, 0.f), fmaxf(th1, 0.f));
}

// ------- layer-2 agg (fp16 z2): lane owns out cols {2*lane, 2*lane+1} --------
__global__ void k_agg2(const float* __restrict__ b2, float* __restrict__ out) {
    int w = (blockIdx.x * blockDim.x + threadIdx.x) >> 5;
    int lane = threadIdx.x & 31;
    if (w >= NN) return;
    int n = w;
    float t00 = 0, t01 = 0, t10 = 0, t11 = 0, t20 = 0, t21 = 0, t30 = 0, t31 = 0;
#pragma unroll
    for (int r = 0; r < RR; r++) {
        int beg = g_rowoff[r * (NN + 1) + n];
        int end = g_rowoff[r * (NN + 1) + n + 1];
        if (beg == end) continue;
        const float4 erd = *reinterpret_cast<const float4*>(&g_er2[(r * NN + n) * 4]);
        float d0 = 0, d1 = 0, d2 = 0, d3 = 0;
        float a00 = 0, a01 = 0, a10 = 0, a11 = 0, a20 = 0, a21 = 0, a30 = 0, a31 = 0;
        for (int i = beg; i < end; i++) {
            int s = g_col[(size_t)r * EE + i];
            float4 el = *reinterpret_cast<const float4*>(&g_el2[(r * NN + s) * 4]);
            float w0 = __expf(lrelu(el.x + erd.x));
            float w1 = __expf(lrelu(el.y + erd.y));
            float w2 = __expf(lrelu(el.z + erd.z));
            float w3 = __expf(lrelu(el.w + erd.w));
            d0 += w0; d1 += w1; d2 += w2; d3 += w3;
            const __half2* z = reinterpret_cast<const __half2*>(
                &g_z2h[((size_t)(r * NN + s)) * F2]);
            float2 f0 = __half22float2(z[lane]);
            float2 f1 = __half22float2(z[32 + lane]);
            float2 f2 = __half22float2(z[64 + lane]);
            float2 f3 = __half22float2(z[96 + lane]);
            a00 += w0 * f0.x; a01 += w0 * f0.y;
            a10 += w1 * f1.x; a11 += w1 * f1.y;
            a20 += w2 * f2.x; a21 += w2 * f2.y;
            a30 += w3 * f3.x; a31 += w3 * f3.y;
        }
        t00 += a00 / d0; t01 += a01 / d0;
        t10 += a10 / d1; t11 += a11 / d1;
        t20 += a20 / d2; t21 += a21 / d2;
        t30 += a30 / d3; t31 += a31 / d3;
    }
    int c0 = 2 * lane, c1 = 2 * lane + 1;
    t00 += b2[c0]       + b2[F2 + c0]       + b2[2 * F2 + c0];
    t01 += b2[c1]       + b2[F2 + c1]       + b2[2 * F2 + c1];
    t10 += b2[64 + c0]  + b2[F2 + 64 + c0]  + b2[2 * F2 + 64 + c0];
    t11 += b2[64 + c1]  + b2[F2 + 64 + c1]  + b2[2 * F2 + 64 + c1];
    t20 += b2[128 + c0] + b2[F2 + 128 + c0] + b2[2 * F2 + 128 + c0];
    t21 += b2[128 + c1] + b2[F2 + 128 + c1] + b2[2 * F2 + 128 + c1];
    t30 += b2[192 + c0] + b2[F2 + 192 + c0] + b2[2 * F2 + 192 + c0];
    t31 += b2[192 + c1] + b2[F2 + 192 + c1] + b2[2 * F2 + 192 + c1];
    *reinterpret_cast<float2*>(&out[(size_t)n * 64 + c0]) =
        make_float2(0.25f * (t00 + t10 + t20 + t30),
                    0.25f * (t01 + t11 + t21 + t31));
}

// ---------------- launch (single stream) -------------------------------------
extern "C" void kernel_launch(void* const* d_in, const int* in_sizes, int n_in,
                              void* d_out, int out_size) {
    const float* x   = (const float*)d_in[0];
    const int*   src = (const int*)d_in[1];
    const int*   dst = (const int*)d_in[2];
    const float* W1  = (const float*)d_in[3];
    const float* al1 = (const float*)d_in[4];
    const float* ar1 = (const float*)d_in[5];
    const float* b1  = (const float*)d_in[6];
    const float* W2  = (const float*)d_in[7];
    const float* al2 = (const float*)d_in[8];
    const float* ar2 = (const float*)d_in[9];
    const float* b2  = (const float*)d_in[10];
    float* out = (float*)d_out;

    __half* w1t; cudaGetSymbolAddress((void**)&w1t, g_w1t);
    __half* w2t; cudaGetSymbolAddress((void**)&w2t, g_w2t);

    // weight transposes (tiny)
    k_transw<<<dim3((KIN * F1 + 255) / 256, RR), 256>>>(W1, w1t, KIN, F1);
    k_transw<<<dim3((F1 * F2 + 255) / 256, RR), 256>>>(W2, w2t, F1, F2);

    // CSR by dst, per relation
    k_zero<<<(RR * NN + 255) / 256, 256>>>();
    k_hist<<<(RR * EE + 255) / 256, 256>>>(dst);
    k_scan<<<RR, 1024>>>();
    k_scatter<<<(RR * EE + 255) / 256, 256>>>(src, dst);

    // layer 1
    dim3 g1(F1 / 128, (NN + 127) / 128, RR);
    k_sgemm_h<<<g1, 256>>>(x, w1t, NN, KIN, F1, 1);
    k_attn1<<<(NN * RR + 7) / 8, 256>>>(al1, ar1);
    k_agg1<<<(NN + 3) / 4, 128>>>(b1);

    // layer 2
    dim3 g2(F2 / 128, (NN + 127) / 128, RR);
    k_sgemm_h<<<g2, 256>>>(nullptr, w2t, NN, F1, F2, 2);
    k_attn2<<<(NN * RR + 7) / 8, 256>>>(al2, ar2);
    k_agg2<<<(NN + 3) / 4, 128>>>(b2, out);
}